// round 1
// baseline (speedup 1.0000x reference)
#include <cuda_runtime.h>
#include <math.h>

#define H      1024
#define SLEN   128
#define VOCAB  32000
#define STEPS  51
#define EOS_ID 2
#define RPB    16            // logits rows per block
#define NPART  (VOCAB/RPB)   // 2000 partial-argmax slots

// ---------------- persistent device state (re-initialized every launch) ----------------
__device__ float g_hbuf[2][H];
__device__ float g_c[H];
__device__ float g_hs[SLEN * H];   // encoder outputs
__device__ float g_d[H];           // attention context
__device__ float g_htnew[H];       // tanh(W_tl @ [d;ht])
__device__ float g_pval[NPART];
__device__ int   g_pidx[NPART];
__device__ int   g_wid;
__device__ int   g_done;

// ---------------- init ----------------
__global__ void k_init() {
    int t = threadIdx.x;            // 1024 threads
    g_hbuf[0][t] = 0.f;
    g_c[t] = 0.f;
    if (t == 0) g_done = 0;
}

__device__ __forceinline__ float sigf(float x) { return 1.f / (1.f + expf(-x)); }

// ---------------- fused LSTM cell step ----------------
// grid = H blocks (one per hidden unit j), 256 threads.
// gates rows j, j+H, j+2H, j+3H of W_ih/W_hh; x = table[row], row from idxp or g_wid.
// Reads h from g_hbuf[hin], writes g_hbuf[hout][j]; c in place (block j touches only c[j]).
__global__ void k_lstm(const float* __restrict__ Wih, const float* __restrict__ Whh,
                       const float* __restrict__ bih, const float* __restrict__ bhh,
                       const float* __restrict__ table, const int* __restrict__ idxp,
                       int hin, int hout, int hs_t)
{
    const int j = blockIdx.x;
    const int t = threadIdx.x;      // 0..255, each owns one float4 slice of H
    const int row = idxp ? *idxp : g_wid;

    const float4* x4p = (const float4*)(table + (size_t)row * H);
    const float4* h4p = (const float4*)g_hbuf[hin];
    const float4 x4 = x4p[t];
    const float4 h4 = h4p[t];

    float acc[4];
#pragma unroll
    for (int g = 0; g < 4; g++) {
        const float4* wi = (const float4*)(Wih + (size_t)(g * H + j) * H);
        const float4* wh = (const float4*)(Whh + (size_t)(g * H + j) * H);
        float4 a = wi[t], b = wh[t];
        acc[g] = a.x * x4.x + a.y * x4.y + a.z * x4.z + a.w * x4.w
               + b.x * h4.x + b.y * h4.y + b.z * h4.z + b.w * h4.w;
    }

    __shared__ float sred[4][256];
#pragma unroll
    for (int g = 0; g < 4; g++) sred[g][t] = acc[g];
    __syncthreads();
    for (int st = 128; st > 0; st >>= 1) {
        if (t < st) {
#pragma unroll
            for (int g = 0; g < 4; g++) sred[g][t] += sred[g][t + st];
        }
        __syncthreads();
    }

    if (t == 0) {
        float gi = sred[0][0] + bih[j]         + bhh[j];
        float gf = sred[1][0] + bih[H + j]     + bhh[H + j];
        float gg = sred[2][0] + bih[2 * H + j] + bhh[2 * H + j];
        float go = sred[3][0] + bih[3 * H + j] + bhh[3 * H + j];
        float i_ = sigf(gi);
        float f_ = sigf(gf);
        float g_ = tanhf(gg);
        float o_ = sigf(go);
        float c2 = f_ * g_c[j] + i_ * g_;
        g_c[j] = c2;
        float hn = o_ * tanhf(c2);
        g_hbuf[hout][j] = hn;
        if (hs_t >= 0) g_hs[(size_t)hs_t * H + j] = hn;
    }
}

// ---------------- attention: scores -> softmax -> context ----------------
// single block, 1024 threads
__global__ void k_att(int hsel)
{
    __shared__ float sa[SLEN];
    const int tid = threadIdx.x;
    const int warp = tid >> 5, lane = tid & 31;
    const float* ht = g_hbuf[hsel];

    // scores[s] = dot(hs[s], ht) : one warp per s (32 warps, 4 rounds)
    for (int s = warp; s < SLEN; s += 32) {
        const float* r = g_hs + (size_t)s * H;
        float acc = 0.f;
        for (int k = lane; k < H; k += 32) acc += r[k] * ht[k];
        for (int o = 16; o; o >>= 1) acc += __shfl_down_sync(0xffffffffu, acc, o);
        if (!lane) sa[s] = acc;
    }
    __syncthreads();

    // softmax over 128 (warp 0)
    if (warp == 0) {
        float m = -INFINITY;
        for (int s = lane; s < SLEN; s += 32) m = fmaxf(m, sa[s]);
        for (int o = 16; o; o >>= 1) m = fmaxf(m, __shfl_xor_sync(0xffffffffu, m, o));
        float sum = 0.f;
        for (int s = lane; s < SLEN; s += 32) { float e = expf(sa[s] - m); sa[s] = e; sum += e; }
        for (int o = 16; o; o >>= 1) sum += __shfl_xor_sync(0xffffffffu, sum, o);
        float inv = 1.f / sum;
        for (int s = lane; s < SLEN; s += 32) sa[s] *= inv;
    }
    __syncthreads();

    // context d[j] = sum_s a[s] * hs[s][j] ; thread = j (coalesced)
    float acc = 0.f;
    for (int s = 0; s < SLEN; s++) acc += sa[s] * g_hs[(size_t)s * H + tid];
    g_d[tid] = acc;
}

// ---------------- ht_new = tanh(W_tl @ [d ; ht] + b_tl) ----------------
// grid = H blocks, 256 threads
__global__ void k_proj(const float* __restrict__ Wtl, const float* __restrict__ btl, int hsel)
{
    const int j = blockIdx.x;
    const int t = threadIdx.x;
    const float4* w = (const float4*)(Wtl + (size_t)j * 2 * H);
    float4 w1 = w[t], w2 = w[t + 256];
    float4 d4 = ((const float4*)g_d)[t];
    float4 h4 = ((const float4*)g_hbuf[hsel])[t];
    float acc = w1.x * d4.x + w1.y * d4.y + w1.z * d4.z + w1.w * d4.w
              + w2.x * h4.x + w2.y * h4.y + w2.z * h4.z + w2.w * h4.w;

    __shared__ float sred[256];
    sred[t] = acc;
    __syncthreads();
    for (int st = 128; st > 0; st >>= 1) {
        if (t < st) sred[t] += sred[t + st];
        __syncthreads();
    }
    if (t == 0) g_htnew[j] = tanhf(sred[0] + btl[j]);
}

// ---------------- logits GEMV + per-block argmax partials ----------------
// grid = NPART blocks of 256 threads; block handles RPB=16 rows (8 warps x 2)
// vecsel: 0/1 -> g_hbuf[vecsel], 2 -> g_htnew. out_logits may be null.
__global__ void k_logits(const float* __restrict__ W, const float* __restrict__ bias,
                         int vecsel, float* __restrict__ out_logits)
{
    const int warp = threadIdx.x >> 5, lane = threadIdx.x & 31;
    const int base = blockIdx.x * RPB;
    const float* vec = (vecsel == 2) ? g_htnew : g_hbuf[vecsel];
    const float4* x = (const float4*)vec;

    __shared__ float svals[RPB];

    for (int r = warp; r < RPB; r += 8) {
        const int v = base + r;
        const float4* w = (const float4*)(W + (size_t)v * H);
        float acc = 0.f;
#pragma unroll
        for (int k = lane; k < 256; k += 32) {
            float4 a = w[k], b = x[k];
            acc += a.x * b.x + a.y * b.y + a.z * b.z + a.w * b.w;
        }
        for (int o = 16; o; o >>= 1) acc += __shfl_down_sync(0xffffffffu, acc, o);
        if (!lane) {
            float lg = acc + bias[v];
            svals[r] = lg;
            if (out_logits) out_logits[v] = lg;
        }
    }
    __syncthreads();
    if (threadIdx.x == 0) {
        float bv = svals[0]; int bi = base;
        for (int r = 1; r < RPB; r++)
            if (svals[r] > bv) { bv = svals[r]; bi = base + r; }   // strict > keeps lowest idx
        g_pval[blockIdx.x] = bv;
        g_pidx[blockIdx.x] = bi;
    }
}

// ---------------- final argmax + token emit + state update ----------------
// 1 block, 256 threads. step=-1: initial word (no token emitted).
__global__ void k_argmax(int step, float* __restrict__ out_toks)
{
    const int t = threadIdx.x;
    float bv = -INFINITY; int bi = 0x7fffffff;
    for (int p = t; p < NPART; p += 256) {
        float v = g_pval[p]; int i = g_pidx[p];
        if (v > bv || (v == bv && i < bi)) { bv = v; bi = i; }
    }
    __shared__ float sv[256];
    __shared__ int   si[256];
    sv[t] = bv; si[t] = bi;
    __syncthreads();
    for (int st = 128; st > 0; st >>= 1) {
        if (t < st) {
            float v = sv[t + st]; int i = si[t + st];
            if (v > sv[t] || (v == sv[t] && i < si[t])) { sv[t] = v; si[t] = i; }
        }
        __syncthreads();
    }
    if (t == 0) {
        int wid = si[0];
        int done_prev = (step >= 0) ? g_done : 0;
        int is_eos = (wid == EOS_ID);
        if (step >= 0)
            out_toks[step] = (float)((done_prev || is_eos) ? -1 : wid);
        g_wid = wid;
        g_done = done_prev | is_eos;
    }
}

// ---------------- host orchestration (graph-capturable: launches only) ----------------
extern "C" void kernel_launch(void* const* d_in, const int* in_sizes, int n_in,
                              void* d_out, int out_size)
{
    const int*   src  = (const int*)  d_in[0];
    const float* embI = (const float*)d_in[1];
    const float* WihE = (const float*)d_in[2];
    const float* WhhE = (const float*)d_in[3];
    const float* bihE = (const float*)d_in[4];
    const float* bhhE = (const float*)d_in[5];
    const float* Wli  = (const float*)d_in[6];
    const float* bli  = (const float*)d_in[7];
    const float* embT = (const float*)d_in[8];
    const float* WihD = (const float*)d_in[9];
    const float* WhhD = (const float*)d_in[10];
    const float* bihD = (const float*)d_in[11];
    const float* bhhD = (const float*)d_in[12];
    const float* Wlt  = (const float*)d_in[13];
    const float* blt  = (const float*)d_in[14];
    const float* Wtl  = (const float*)d_in[15];
    const float* btl  = (const float*)d_in[16];

    float* out        = (float*)d_out;
    float* out_logits = out + STEPS;   // [51 toks][51 x 32000 logits]

    k_init<<<1, 1024>>>();

    // ---- encoder: 128 sequential LSTM cells; h ping-pongs, ends in buf 0 ----
    for (int t = 0; t < SLEN; t++)
        k_lstm<<<H, 256>>>(WihE, WhhE, bihE, bhhE, embI, src + t, t & 1, (t + 1) & 1, t);

    // ---- first word from final encoder state ----
    k_logits<<<NPART, 256>>>(Wli, bli, /*vecsel=*/0, nullptr);
    k_argmax<<<1, 256>>>(-1, out);

    // ---- initial decoder LSTM: x = embed_target[wid0], state (hs, cx) ----
    k_lstm<<<H, 256>>>(WihD, WhhD, bihD, bhhD, embT, nullptr, 0, 1, -1);
    int cur = 1;

    // ---- 51 greedy decode steps ----
    for (int t = 0; t < STEPS; t++) {
        k_att<<<1, 1024>>>(cur);
        k_proj<<<H, 256>>>(Wtl, btl, cur);
        // LSTM consumes wid_{t-1} (g_wid not yet updated this step) and old ht
        k_lstm<<<H, 256>>>(WihD, WhhD, bihD, bhhD, embT, nullptr, cur, 1 - cur, -1);
        k_logits<<<NPART, 256>>>(Wlt, blt, /*vecsel=*/2, out_logits + (size_t)t * VOCAB);
        k_argmax<<<1, 256>>>(t, out);
        cur ^= 1;
    }
}

// round 2
// speedup vs baseline: 1.1915x; 1.1915x over previous
#include <cuda_runtime.h>
#include <math.h>

#define H      1024
#define SLEN   128
#define VOCAB  32000
#define STEPS  51
#define EOS_ID 2
#define GRID   512
#define TPB    256
#define NWARP  8

// ---------------- persistent device state ----------------
__device__ float g_hbuf[2][H];
__device__ float g_c[H];
__device__ float g_hs[SLEN * H];
__device__ float g_scores[SLEN];
__device__ float g_d[H];
__device__ float g_htnew[H];
__device__ float g_pval[GRID];
__device__ int   g_pidx[GRID];
__device__ int   g_wid;
__device__ int   g_done;
__device__ unsigned int g_bar_count;
__device__ volatile unsigned int g_bar_phase;

__global__ void k_init() {
    int t = threadIdx.x;             // 1024 threads
    g_hbuf[0][t] = 0.f;
    g_c[t] = 0.f;
    if (t == 0) { g_done = 0; g_bar_count = 0u; g_bar_phase = 0u; }
}

// ---------------- grid-wide barrier (all 512 blocks resident by construction) ----------------
__device__ __forceinline__ void gbar(unsigned int& gen) {
    __threadfence();                 // release: every thread publishes its writes
    __syncthreads();
    gen++;
    if (threadIdx.x == 0) {
        unsigned int prev = atomicAdd(&g_bar_count, 1u);
        if (prev == GRID - 1u) {
            g_bar_count = 0u;
            __threadfence();
            g_bar_phase = gen;
        } else {
            while (g_bar_phase < gen) { }
        }
    }
    __syncthreads();
    __threadfence();                 // acquire side
}

__device__ __forceinline__ float sigf(float x) { return 1.f / (1.f + expf(-x)); }
__device__ __forceinline__ float dp4(float4 a, float4 b) {
    return a.x * b.x + a.y * b.y + a.z * b.z + a.w * b.w;
}
__device__ __forceinline__ float wred(float v) {
#pragma unroll
    for (int o = 16; o; o >>= 1) v += __shfl_down_sync(0xffffffffu, v, o);
    return v;
}

// ---------------- LSTM phase: warp-per-gate-row, fused pointwise ----------------
// JPB = hidden units per block. JPB=2 -> 512 active blocks, JPB=4 -> 256 active blocks.
template <int JPB>
__device__ void lstm_phase(const float* __restrict__ Wih, const float* __restrict__ Whh,
                           const float* __restrict__ bih, const float* __restrict__ bhh,
                           const float* __restrict__ x,   const float* __restrict__ hprev,
                           float* __restrict__ hnext, float* __restrict__ hs_out,
                           float* s_g)
{
    const int NB = H / JPB;
    const int b = blockIdx.x;
    if (b >= NB) return;
    const int tid = threadIdx.x, w = tid >> 5, lane = tid & 31;
    const int TPW = (JPB * 4) / NWARP;               // tasks per warp (1 or 2)
    const float4* x4 = (const float4*)x;
    const float4* h4 = (const float4*)hprev;
#pragma unroll
    for (int k = 0; k < TPW; k++) {
        const int task = w * TPW + k;                // task = jj*4 + g
        const int jj = task >> 2, g = task & 3;
        const int j = b * JPB + jj;
        const float4* wi = (const float4*)(Wih + (size_t)(g * H + j) * H);
        const float4* wh = (const float4*)(Whh + (size_t)(g * H + j) * H);
        float acc = 0.f;
#pragma unroll
        for (int i = 0; i < 8; i++) acc += dp4(wi[lane + 32 * i], x4[lane + 32 * i]);
#pragma unroll
        for (int i = 0; i < 8; i++) acc += dp4(wh[lane + 32 * i], h4[lane + 32 * i]);
        acc = wred(acc);
        if (!lane) s_g[task] = acc;
    }
    __syncthreads();
    if (tid < JPB) {
        const int j = b * JPB + tid;
        float gi = s_g[tid * 4 + 0] + bih[j]         + bhh[j];
        float gf = s_g[tid * 4 + 1] + bih[H + j]     + bhh[H + j];
        float gg = s_g[tid * 4 + 2] + bih[2 * H + j] + bhh[2 * H + j];
        float go = s_g[tid * 4 + 3] + bih[3 * H + j] + bhh[3 * H + j];
        float i_ = sigf(gi), f_ = sigf(gf), g_ = tanhf(gg), o_ = sigf(go);
        float c2 = f_ * g_c[j] + i_ * g_;
        g_c[j] = c2;
        float hn = o_ * tanhf(c2);
        hnext[j] = hn;
        if (hs_out) hs_out[j] = hn;
    }
}

// ---------------- attention scores: blocks 1..128, one per source position ----------------
__device__ void scores_phase(const float* __restrict__ ht, float* s_red)
{
    const int b = blockIdx.x;
    if (b < 1 || b > SLEN) return;
    const int s = b - 1;
    const int tid = threadIdx.x, w = tid >> 5, lane = tid & 31;
    const float4* r  = (const float4*)(g_hs + (size_t)s * H);
    const float4* h4 = (const float4*)ht;
    float acc = dp4(r[tid], h4[tid]);
    acc = wred(acc);
    if (!lane) s_red[w] = acc;
    __syncthreads();
    if (tid == 0) {
        float t = 0.f;
#pragma unroll
        for (int q = 0; q < NWARP; q++) t += s_red[q];
        g_scores[s] = t;
    }
}

// ---------------- softmax + context: blocks 0..3, thread = output column ----------------
__device__ void context_phase(float* s_sc, float* s_a, float* s_scalar)
{
    const int b = blockIdx.x;
    if (b >= 4) return;
    const int tid = threadIdx.x, w = tid >> 5, lane = tid & 31;
    if (tid < SLEN) s_sc[tid] = g_scores[tid];
    __syncthreads();
    if (w == 0) {
        float m = -INFINITY;
#pragma unroll
        for (int q = 0; q < 4; q++) m = fmaxf(m, s_sc[lane + 32 * q]);
#pragma unroll
        for (int o = 16; o; o >>= 1) m = fmaxf(m, __shfl_xor_sync(0xffffffffu, m, o));
        float sum = 0.f;
#pragma unroll
        for (int q = 0; q < 4; q++) {
            float e = expf(s_sc[lane + 32 * q] - m);
            s_a[lane + 32 * q] = e;
            sum += e;
        }
#pragma unroll
        for (int o = 16; o; o >>= 1) sum += __shfl_xor_sync(0xffffffffu, sum, o);
        if (!lane) s_scalar[0] = 1.f / sum;
    }
    __syncthreads();
    const float inv = s_scalar[0];
    const int j = b * TPB + tid;
    float acc = 0.f;
#pragma unroll 8
    for (int s = 0; s < SLEN; s++) acc += s_a[s] * g_hs[(size_t)s * H + j];
    g_d[j] = acc * inv;
}

// ---------------- ht_new = tanh(W_tl @ [d;ht] + b): blocks 256..511, warp-per-row ----------------
__device__ void proj_phase(const float* __restrict__ Wtl, const float* __restrict__ btl,
                           const float* __restrict__ ht)
{
    const int b = blockIdx.x;
    if (b < 256) return;
    const int w = threadIdx.x >> 5, lane = threadIdx.x & 31;
    const int gw = (b - 256) * NWARP + w;
    if (gw >= H) return;
    const float4* wr = (const float4*)(Wtl + (size_t)gw * 2 * H);
    const float4* d4 = (const float4*)g_d;
    const float4* h4 = (const float4*)ht;
    float acc = 0.f;
#pragma unroll
    for (int i = 0; i < 8; i++) acc += dp4(wr[lane + 32 * i], d4[lane + 32 * i]);
#pragma unroll
    for (int i = 0; i < 8; i++) acc += dp4(wr[256 + lane + 32 * i], h4[lane + 32 * i]);
    acc = wred(acc);
    if (!lane) g_htnew[gw] = tanhf(acc + btl[gw]);
}

// ---------------- logits GEMV + per-block argmax partial: all 512 blocks ----------------
__device__ void logits_phase(const float* __restrict__ W, const float* __restrict__ bias,
                             const float* __restrict__ vec, float* __restrict__ out_logits,
                             float* s_v, int* s_i)
{
    const int tid = threadIdx.x, w = tid >> 5, lane = tid & 31;
    const float4* x4 = (const float4*)vec;
    float4 v[8];
#pragma unroll
    for (int q = 0; q < 8; q++) v[q] = x4[lane + 32 * q];
    const int gw = blockIdx.x * NWARP + w;           // 4096 warps
    float best = -INFINITY; int bidx = VOCAB;
#pragma unroll
    for (int i = 0; i < 8; i++) {
        const int r = gw + 4096 * i;                 // ascending -> strict > keeps lowest idx
        if (r < VOCAB) {
            const float4* wr = (const float4*)(W + (size_t)r * H);
            float acc = 0.f;
#pragma unroll
            for (int q = 0; q < 8; q++) acc += dp4(wr[lane + 32 * q], v[q]);
            acc = wred(acc);
            if (!lane) {
                float lg = acc + bias[r];
                if (out_logits) out_logits[r] = lg;
                if (lg > best) { best = lg; bidx = r; }
            }
        }
    }
    if (!lane) { s_v[w] = best; s_i[w] = bidx; }
    __syncthreads();
    if (tid == 0) {
        float bv = s_v[0]; int bi = s_i[0];
#pragma unroll
        for (int q = 1; q < NWARP; q++)
            if (s_v[q] > bv || (s_v[q] == bv && s_i[q] < bi)) { bv = s_v[q]; bi = s_i[q]; }
        g_pval[blockIdx.x] = bv; g_pidx[blockIdx.x] = bi;
    }
}

// ---------------- final argmax + token emit + state update: block 0 only ----------------
__device__ void finalize_phase(int step, float* __restrict__ out_toks, float* s_v, int* s_i)
{
    if (blockIdx.x != 0) return;
    const int t = threadIdx.x;
    float bv = g_pval[t];       int bi = g_pidx[t];
    float v2 = g_pval[t + 256]; int i2 = g_pidx[t + 256];
    if (v2 > bv || (v2 == bv && i2 < bi)) { bv = v2; bi = i2; }
    s_v[t] = bv; s_i[t] = bi;
    __syncthreads();
    for (int st = 128; st > 0; st >>= 1) {
        if (t < st) {
            float v = s_v[t + st]; int i = s_i[t + st];
            if (v > s_v[t] || (v == s_v[t] && i < s_i[t])) { s_v[t] = v; s_i[t] = i; }
        }
        __syncthreads();
    }
    if (t == 0) {
        int wid = s_i[0];
        int done_prev = (step >= 0) ? g_done : 0;
        int is_eos = (wid == EOS_ID);
        if (step >= 0) out_toks[step] = (float)((done_prev || is_eos) ? -1 : wid);
        g_wid = wid;
        g_done = done_prev | is_eos;
    }
}

// ---------------- the whole model in one persistent kernel ----------------
__global__ void __launch_bounds__(TPB, 4) k_main(
    const int* __restrict__ src,
    const float* __restrict__ embI,
    const float* __restrict__ WihE, const float* __restrict__ WhhE,
    const float* __restrict__ bihE, const float* __restrict__ bhhE,
    const float* __restrict__ Wli,  const float* __restrict__ bli,
    const float* __restrict__ embT,
    const float* __restrict__ WihD, const float* __restrict__ WhhD,
    const float* __restrict__ bihD, const float* __restrict__ bhhD,
    const float* __restrict__ Wlt,  const float* __restrict__ blt,
    const float* __restrict__ Wtl,  const float* __restrict__ btl,
    float* __restrict__ out)
{
    __shared__ float s_g[16];
    __shared__ float s_v[256];
    __shared__ int   s_i[256];
    __shared__ float s_sc[SLEN];
    __shared__ float s_a[SLEN];
    __shared__ float s_scalar[1];

    unsigned int gen = 0;
    float* out_logits = out + STEPS;

    // ---- encoder: 128 steps, weights stay L1/L2-hot across steps ----
    for (int t = 0; t < SLEN; t++) {
        const float* x = embI + (size_t)src[t] * H;
        lstm_phase<2>(WihE, WhhE, bihE, bhhE, x, g_hbuf[t & 1], g_hbuf[(t + 1) & 1],
                      g_hs + (size_t)t * H, s_g);
        gbar(gen);
    }

    // ---- first word from final encoder state (hbuf[0]) ----
    logits_phase(Wli, bli, g_hbuf[0], nullptr, s_v, s_i);
    gbar(gen);
    finalize_phase(-1, out, s_v, s_i);
    gbar(gen);

    // ---- initial decoder LSTM: x = embT[wid0], state (h_enc, c_enc) ----
    lstm_phase<2>(WihD, WhhD, bihD, bhhD, embT + (size_t)g_wid * H,
                  g_hbuf[0], g_hbuf[1], nullptr, s_g);
    gbar(gen);

    int cur = 1;
    for (int t = 0; t < STEPS; t++) {
        // P1: attention scores (blocks 1..128) || deferred argmax finalize of step t-1 (block 0)
        scores_phase(g_hbuf[cur], s_v);
        if (t > 0) finalize_phase(t - 1, out, s_v, s_i);
        gbar(gen);
        // P2: softmax + context (blocks 0..3)
        context_phase(s_sc, s_a, s_scalar);
        gbar(gen);
        // P3: decoder LSTM (blocks 0..255, uses wid_{t-1}) || proj (blocks 256..511)
        lstm_phase<4>(WihD, WhhD, bihD, bhhD, embT + (size_t)g_wid * H,
                      g_hbuf[cur], g_hbuf[1 - cur], nullptr, s_g);
        proj_phase(Wtl, btl, g_hbuf[cur]);
        gbar(gen);
        // P4: logits + per-block argmax partials (all 512 blocks)
        logits_phase(Wlt, blt, g_htnew, out_logits + (size_t)t * VOCAB, s_v, s_i);
        gbar(gen);
        cur ^= 1;
    }
    finalize_phase(STEPS - 1, out, s_v, s_i);
}

// ---------------- host orchestration: 2 graph nodes ----------------
extern "C" void kernel_launch(void* const* d_in, const int* in_sizes, int n_in,
                              void* d_out, int out_size)
{
    const int*   src  = (const int*)  d_in[0];
    const float* embI = (const float*)d_in[1];
    const float* WihE = (const float*)d_in[2];
    const float* WhhE = (const float*)d_in[3];
    const float* bihE = (const float*)d_in[4];
    const float* bhhE = (const float*)d_in[5];
    const float* Wli  = (const float*)d_in[6];
    const float* bli  = (const float*)d_in[7];
    const float* embT = (const float*)d_in[8];
    const float* WihD = (const float*)d_in[9];
    const float* WhhD = (const float*)d_in[10];
    const float* bihD = (const float*)d_in[11];
    const float* bhhD = (const float*)d_in[12];
    const float* Wlt  = (const float*)d_in[13];
    const float* blt  = (const float*)d_in[14];
    const float* Wtl  = (const float*)d_in[15];
    const float* btl  = (const float*)d_in[16];

    k_init<<<1, 1024>>>();
    k_main<<<GRID, TPB>>>(src, embI, WihE, WhhE, bihE, bhhE, Wli, bli, embT,
                          WihD, WhhD, bihD, bhhD, Wlt, blt, Wtl, btl,
                          (float*)d_out);
}

// round 3
// speedup vs baseline: 1.5184x; 1.2743x over previous
#include <cuda_runtime.h>
#include <math.h>

#define H      1024
#define SLEN   128
#define VOCAB  32000
#define STEPS  51
#define EOS_ID 2
#define GRID   512
#define TPB    256
#define NWARP  8
#define NWARPS_TOT (GRID * NWARP)    // 4096

// ---------------- persistent device state ----------------
__device__ float g_hbuf[2][H];
__device__ float g_c[H];
__device__ float g_hs[SLEN * H];
__device__ float g_scores[SLEN];
__device__ float g_d[H];
__device__ float g_htnew[H];
__device__ float g_pval[GRID];
__device__ int   g_pidx[GRID];
__device__ int   g_wid;
__device__ int   g_done;
__device__ unsigned int g_bar_count;

__global__ void k_init() {
    int t = threadIdx.x;             // 1024 threads
    g_hbuf[0][t] = 0.f;
    g_c[t] = 0.f;
    if (t == 0) { g_done = 0; g_bar_count = 0u; }
}

// ---------------- grid barrier: 1-thread arrival, acq_rel fences, monotonic count ----------------
__device__ __forceinline__ void gbar(unsigned int& gen) {
    __syncthreads();
    gen += GRID;
    if (threadIdx.x == 0) {
        asm volatile("fence.acq_rel.gpu;" ::: "memory");
        unsigned int prev = atomicAdd(&g_bar_count, 1u);
        if (prev + 1u != gen) {
            while (*(volatile unsigned int*)&g_bar_count < gen) { }
        }
        asm volatile("fence.acq_rel.gpu;" ::: "memory");
    }
    __syncthreads();
}

__device__ __forceinline__ float sigf(float x) { return 1.f / (1.f + expf(-x)); }
__device__ __forceinline__ float dp4(float4 a, float4 b) {
    return a.x * b.x + a.y * b.y + a.z * b.z + a.w * b.w;
}
__device__ __forceinline__ float wred(float v) {
#pragma unroll
    for (int o = 16; o; o >>= 1) v += __shfl_down_sync(0xffffffffu, v, o);
    return v;
}

// ---------------- LSTM pieces (blocks 0..511, task = b*8+w, unit j = b*2 + w/4, gate = w%4) --------
__device__ __forceinline__ void lstm_whh(const float* __restrict__ Whh,
                                         const float* __restrict__ hprev, float* s_g)
{
    const int b = blockIdx.x, w = threadIdx.x >> 5, lane = threadIdx.x & 31;
    const int j = b * 2 + (w >> 2), g = w & 3;
    const float4* wh = (const float4*)(Whh + (size_t)(g * H + j) * H);
    const float4* h4 = (const float4*)hprev;
    float acc = 0.f;
#pragma unroll
    for (int i = 0; i < 8; i++) acc += dp4(wh[lane + 32 * i], h4[lane + 32 * i]);
    acc = wred(acc);
    if (!lane) s_g[w] = acc;
}

__device__ __forceinline__ void lstm_pointwise(const float* __restrict__ bih,
                                               const float* __restrict__ bhh,
                                               float* __restrict__ hnext,
                                               float* __restrict__ hs_out, float* s_g)
{
    __syncthreads();
    const int tid = threadIdx.x;
    if (tid < 2) {
        const int j = blockIdx.x * 2 + tid;
        const int base = tid * 4;
        float gi = s_g[base + 0] + bih[j]         + bhh[j];
        float gf = s_g[base + 1] + bih[H + j]     + bhh[H + j];
        float gg = s_g[base + 2] + bih[2 * H + j] + bhh[2 * H + j];
        float go = s_g[base + 3] + bih[3 * H + j] + bhh[3 * H + j];
        float i_ = sigf(gi), f_ = sigf(gf), g_ = tanhf(gg), o_ = sigf(go);
        float c2 = f_ * g_c[j] + i_ * g_;
        g_c[j] = c2;
        float hn = o_ * tanhf(c2);
        hnext[j] = hn;
        if (hs_out) hs_out[j] = hn;
    }
}

// Wih half: adds x-dot into s_g, then pointwise
__device__ __forceinline__ void lstm_wih_pw(const float* __restrict__ Wih,
                                            const float* __restrict__ xrow,
                                            const float* __restrict__ bih,
                                            const float* __restrict__ bhh,
                                            float* __restrict__ hnext,
                                            float* __restrict__ hs_out, float* s_g)
{
    const int b = blockIdx.x, w = threadIdx.x >> 5, lane = threadIdx.x & 31;
    const int j = b * 2 + (w >> 2), g = w & 3;
    const float4* wi = (const float4*)(Wih + (size_t)(g * H + j) * H);
    const float4* x4 = (const float4*)xrow;
    float acc = 0.f;
#pragma unroll
    for (int i = 0; i < 8; i++) acc += dp4(wi[lane + 32 * i], x4[lane + 32 * i]);
    acc = wred(acc);
    if (!lane) s_g[w] += acc;
    lstm_pointwise(bih, bhh, hnext, hs_out, s_g);
}

// full LSTM (encoder / initial decoder step): both halves in one phase
__device__ __forceinline__ void lstm_full(const float* __restrict__ Wih,
                                          const float* __restrict__ Whh,
                                          const float* __restrict__ bih,
                                          const float* __restrict__ bhh,
                                          const float* __restrict__ xrow,
                                          const float* __restrict__ hprev,
                                          float* __restrict__ hnext,
                                          float* __restrict__ hs_out, float* s_g)
{
    const int b = blockIdx.x, w = threadIdx.x >> 5, lane = threadIdx.x & 31;
    const int j = b * 2 + (w >> 2), g = w & 3;
    const float4* wi = (const float4*)(Wih + (size_t)(g * H + j) * H);
    const float4* wh = (const float4*)(Whh + (size_t)(g * H + j) * H);
    const float4* x4 = (const float4*)xrow;
    const float4* h4 = (const float4*)hprev;
    float acc = 0.f;
#pragma unroll
    for (int i = 0; i < 8; i++) acc += dp4(wi[lane + 32 * i], x4[lane + 32 * i]);
#pragma unroll
    for (int i = 0; i < 8; i++) acc += dp4(wh[lane + 32 * i], h4[lane + 32 * i]);
    acc = wred(acc);
    if (!lane) s_g[w] = acc;
    lstm_pointwise(bih, bhh, hnext, hs_out, s_g);
}

// ---------------- attention scores: 128 warps (blocks 496..511) ----------------
__device__ __forceinline__ void scores_piece(const float* __restrict__ ht)
{
    const int b = blockIdx.x;
    if (b < GRID - 16) return;
    const int w = threadIdx.x >> 5, lane = threadIdx.x & 31;
    const int s = (b - (GRID - 16)) * NWARP + w;     // 0..127
    const float4* r  = (const float4*)(g_hs + (size_t)s * H);
    const float4* h4 = (const float4*)ht;
    float acc = 0.f;
#pragma unroll
    for (int i = 0; i < 8; i++) acc += dp4(r[lane + 32 * i], h4[lane + 32 * i]);
    acc = wred(acc);
    if (!lane) g_scores[s] = acc;
}

// ---------------- softmax + context: blocks 0..3 ----------------
__device__ __forceinline__ void context_piece(float* s_sc, float* s_a, float* s_scalar)
{
    const int b = blockIdx.x;
    if (b >= 4) return;
    const int tid = threadIdx.x, w = tid >> 5, lane = tid & 31;
    if (tid < SLEN) s_sc[tid] = g_scores[tid];
    __syncthreads();
    if (w == 0) {
        float m = -INFINITY;
#pragma unroll
        for (int q = 0; q < 4; q++) m = fmaxf(m, s_sc[lane + 32 * q]);
#pragma unroll
        for (int o = 16; o; o >>= 1) m = fmaxf(m, __shfl_xor_sync(0xffffffffu, m, o));
        float sum = 0.f;
#pragma unroll
        for (int q = 0; q < 4; q++) {
            float e = expf(s_sc[lane + 32 * q] - m);
            s_a[lane + 32 * q] = e;
            sum += e;
        }
#pragma unroll
        for (int o = 16; o; o >>= 1) sum += __shfl_xor_sync(0xffffffffu, sum, o);
        if (!lane) s_scalar[0] = 1.f / sum;
    }
    __syncthreads();
    const float inv = s_scalar[0];
    const int j = b * TPB + threadIdx.x;
    float acc = 0.f;
#pragma unroll 8
    for (int s = 0; s < SLEN; s++) acc += s_a[s] * g_hs[(size_t)s * H + j];
    g_d[j] = acc * inv;
}

// ---------------- proj: blocks 0..127, warp-per-row ----------------
__device__ __forceinline__ void proj_piece(const float* __restrict__ Wtl,
                                           const float* __restrict__ btl,
                                           const float* __restrict__ ht)
{
    const int b = blockIdx.x;
    if (b >= 128) return;
    const int w = threadIdx.x >> 5, lane = threadIdx.x & 31;
    const int r = b * NWARP + w;                     // 0..1023
    const float4* wr = (const float4*)(Wtl + (size_t)r * 2 * H);
    const float4* d4 = (const float4*)g_d;
    const float4* h4 = (const float4*)ht;
    float acc = 0.f;
#pragma unroll
    for (int i = 0; i < 8; i++) acc += dp4(wr[lane + 32 * i], d4[lane + 32 * i]);
#pragma unroll
    for (int i = 0; i < 8; i++) acc += dp4(wr[256 + lane + 32 * i], h4[lane + 32 * i]);
    acc = wred(acc);
    if (!lane) g_htnew[r] = tanhf(acc + btl[r]);
}

// ---------------- logits GEMV (streaming loads) + per-block argmax partial ----------------
__device__ __forceinline__ void logits_piece(const float* __restrict__ W,
                                             const float* __restrict__ bias,
                                             const float* __restrict__ vec,
                                             float* __restrict__ out_logits,
                                             float* s_v, int* s_i)
{
    const int tid = threadIdx.x, w = tid >> 5, lane = tid & 31;
    const float4* x4 = (const float4*)vec;
    float4 v[8];
#pragma unroll
    for (int q = 0; q < 8; q++) v[q] = x4[lane + 32 * q];
    const int gw = blockIdx.x * NWARP + w;           // 0..4095
    float best = -INFINITY; int bidx = VOCAB;
#pragma unroll
    for (int i = 0; i < 8; i++) {
        const int r = gw + NWARPS_TOT * i;           // ascending -> strict > keeps lowest idx
        if (r < VOCAB) {
            const float4* wr = (const float4*)(W + (size_t)r * H);
            float acc = 0.f;
#pragma unroll
            for (int q = 0; q < 8; q++) acc += dp4(__ldcs(wr + lane + 32 * q), v[q]);
            acc = wred(acc);
            if (!lane) {
                float lg = acc + bias[r];
                if (out_logits) __stcs(out_logits + r, lg);
                if (lg > best) { best = lg; bidx = r; }
            }
        }
    }
    if (!lane) { s_v[w] = best; s_i[w] = bidx; }
    __syncthreads();
    if (tid == 0) {
        float bv = s_v[0]; int bi = s_i[0];
#pragma unroll
        for (int q = 1; q < NWARP; q++)
            if (s_v[q] > bv || (s_v[q] == bv && s_i[q] < bi)) { bv = s_v[q]; bi = s_i[q]; }
        g_pval[blockIdx.x] = bv; g_pidx[blockIdx.x] = bi;
    }
}

// ---------------- final argmax + token emit (block 4) ----------------
__device__ __forceinline__ void finalize_piece(int step, float* __restrict__ out_toks,
                                               float* s_v, int* s_i)
{
    if (blockIdx.x != 4) return;
    const int t = threadIdx.x;
    float bv = g_pval[t];       int bi = g_pidx[t];
    float v2 = g_pval[t + 256]; int i2 = g_pidx[t + 256];
    if (v2 > bv || (v2 == bv && i2 < bi)) { bv = v2; bi = i2; }
    s_v[t] = bv; s_i[t] = bi;
    __syncthreads();
    for (int st = 128; st > 0; st >>= 1) {
        if (t < st) {
            float v = s_v[t + st]; int i = s_i[t + st];
            if (v > s_v[t] || (v == s_v[t] && i < s_i[t])) { s_v[t] = v; s_i[t] = i; }
        }
        __syncthreads();
    }
    if (t == 0) {
        int wid = s_i[0];
        int done_prev = (step >= 0) ? g_done : 0;
        int is_eos = (wid == EOS_ID);
        if (step >= 0) out_toks[step] = (float)((done_prev || is_eos) ? -1 : wid);
        g_wid = wid;
        g_done = done_prev | is_eos;
    }
}

// ---------------- the whole model, one persistent kernel ----------------
__global__ void __launch_bounds__(TPB, 4) k_main(
    const int* __restrict__ src,
    const float* __restrict__ embI,
    const float* __restrict__ WihE, const float* __restrict__ WhhE,
    const float* __restrict__ bihE, const float* __restrict__ bhhE,
    const float* __restrict__ Wli,  const float* __restrict__ bli,
    const float* __restrict__ embT,
    const float* __restrict__ WihD, const float* __restrict__ WhhD,
    const float* __restrict__ bihD, const float* __restrict__ bhhD,
    const float* __restrict__ Wlt,  const float* __restrict__ blt,
    const float* __restrict__ Wtl,  const float* __restrict__ btl,
    float* __restrict__ out)
{
    __shared__ float s_g[8];         // gate partials; PERSISTS across the P1->P2 grid barrier
    __shared__ float s_v[256];
    __shared__ int   s_i[256];
    __shared__ float s_sc[SLEN];
    __shared__ float s_a[SLEN];
    __shared__ float s_scalar[1];

    unsigned int gen = 0;
    float* out_logits = out + STEPS;

    // ---- encoder: 128 sequential full-LSTM phases ----
    for (int t = 0; t < SLEN; t++) {
        lstm_full(WihE, WhhE, bihE, bhhE, embI + (size_t)src[t] * H,
                  g_hbuf[t & 1], g_hbuf[(t + 1) & 1], g_hs + (size_t)t * H, s_g);
        gbar(gen);
    }
    // final encoder h in g_hbuf[0], c in g_c

    // ---- first word ----
    logits_piece(Wli, bli, g_hbuf[0], nullptr, s_v, s_i);
    gbar(gen);
    finalize_piece(-1, out, s_v, s_i);               // sets g_wid = wid0, g_done
    gbar(gen);

    // ---- initial decoder LSTM: ht(step0) -> g_hbuf[1] ----
    lstm_full(WihD, WhhD, bihD, bhhD, embT + (size_t)g_wid * H,
              g_hbuf[0], g_hbuf[1], nullptr, s_g);
    gbar(gen);

    // ---- scores for step 0 ----
    scores_piece(g_hbuf[1]);
    gbar(gen);

    int cur = 1;
    for (int t = 0; t < STEPS; t++) {
        const float* ht   = g_hbuf[cur];
        float*       htn  = g_hbuf[1 - cur];

        // P1: LSTM Whh half (all 512 blocks) || context (blocks 0..3) || finalize(t-1) (block 4)
        lstm_whh(WhhD, ht, s_g);
        context_piece(s_sc, s_a, s_scalar);
        if (t > 0) finalize_piece(t - 1, out, s_v, s_i);
        gbar(gen);

        // P2: LSTM Wih half + pointwise -> ht_{t+1} (uses wid_{t-1}) || proj (blocks 0..127)
        lstm_wih_pw(WihD, embT + (size_t)g_wid * H, bihD, bhhD, htn, nullptr, s_g);
        proj_piece(Wtl, btl, ht);
        gbar(gen);

        // P3: logits (all blocks, streaming) || scores(t+1) from ht_{t+1} (blocks 496..511)
        scores_piece(htn);
        logits_piece(Wlt, blt, g_htnew, out_logits + (size_t)t * VOCAB, s_v, s_i);
        gbar(gen);

        cur ^= 1;
    }
    finalize_piece(STEPS - 1, out, s_v, s_i);
}

// ---------------- host orchestration ----------------
extern "C" void kernel_launch(void* const* d_in, const int* in_sizes, int n_in,
                              void* d_out, int out_size)
{
    const int*   src  = (const int*)  d_in[0];
    const float* embI = (const float*)d_in[1];
    const float* WihE = (const float*)d_in[2];
    const float* WhhE = (const float*)d_in[3];
    const float* bihE = (const float*)d_in[4];
    const float* bhhE = (const float*)d_in[5];
    const float* Wli  = (const float*)d_in[6];
    const float* bli  = (const float*)d_in[7];
    const float* embT = (const float*)d_in[8];
    const float* WihD = (const float*)d_in[9];
    const float* WhhD = (const float*)d_in[10];
    const float* bihD = (const float*)d_in[11];
    const float* bhhD = (const float*)d_in[12];
    const float* Wlt  = (const float*)d_in[13];
    const float* blt  = (const float*)d_in[14];
    const float* Wtl  = (const float*)d_in[15];
    const float* btl  = (const float*)d_in[16];

    k_init<<<1, 1024>>>();
    k_main<<<GRID, TPB>>>(src, embI, WihE, WhhE, bihE, bhhE, Wli, bli, embT,
                          WihD, WhhD, bihD, bhhD, Wlt, blt, Wtl, btl,
                          (float*)d_out);
}